// round 16
// baseline (speedup 1.0000x reference)
#include <cuda_runtime.h>
#include <cuda_bf16.h>
#include <stdint.h>

// ---------------- problem constants ----------------------------------------
#define NB   32
#define HH   56
#define WW   56
#define CI   256
#define CO   256
#define HP   58
#define WP   58
#define NW_ELEM (9*CI*CO)        // 589824
#define NTPI 784                 // 28x28 tiles per image
#define NT   (NB*NTPI)           // 25088 Winograd tiles
#define NKS  16                  // K = 256 in 16-element bf16 steps (32 B)

#define NSTG        3
#define ROWPAD      48
#define A_SZ        (64*ROWPAD)              // 3072  (64 tile rows)
#define STAGE_B     (A_SZ + 256*ROWPAD)      // 3072 + 12288 = 15360

// ---------------- device scratch --------------------------------------------
__device__ int            g_act[NB * HP * WP * 64];        // padded s8 acts, 27.5 MB
__device__ __nv_bfloat16  g_V[(size_t)16 * NT * CI];       // transformed acts, 205 MB
__device__ __nv_bfloat16  g_U[16 * CO * CI];               // transformed weights, 2 MB
__device__ float          g_C[(size_t)16 * NT * CO];       // GEMM out fp32, 411 MB
__device__ float g_partial[576];
__device__ float g_E;

// ---------------- PTX helpers ------------------------------------------------
__device__ __forceinline__ uint32_t smem_u32(const void* p) {
    uint32_t a;
    asm("{ .reg .u64 t; cvta.to.shared.u64 t, %1; cvt.u32.u64 %0, t; }" : "=r"(a) : "l"(p));
    return a;
}
#define CP_ASYNC16(dst, src) \
    asm volatile("cp.async.cg.shared.global [%0], [%1], 16;" \
        :: "r"(dst), "l"(__cvta_generic_to_global(src)))
#define CP_COMMIT() asm volatile("cp.async.commit_group;" ::: "memory")
#define CP_WAIT(n)  asm volatile("cp.async.wait_group %0;" :: "n"(n) : "memory")

__device__ __forceinline__ void hmma16816(float* d, uint32_t a0, uint32_t a1,
                                          uint32_t a2, uint32_t a3,
                                          uint32_t b0, uint32_t b1) {
    asm volatile(
        "mma.sync.aligned.m16n8k16.row.col.f32.bf16.bf16.f32 "
        "{%0,%1,%2,%3}, {%4,%5,%6,%7}, {%8,%9}, {%0,%1,%2,%3};"
        : "+f"(d[0]), "+f"(d[1]), "+f"(d[2]), "+f"(d[3])
        : "r"(a0), "r"(a1), "r"(a2), "r"(a3), "r"(b0), "r"(b1));
}

// ---------------- 1a/1b. E = mean|W| -----------------------------------------
__global__ void __launch_bounds__(256) reduce_absw_1(const float* __restrict__ W) {
    __shared__ float sh[256];
    int b = blockIdx.x, t = threadIdx.x;
    const float* p = W + b * 1024;
    sh[t] = fabsf(p[t]) + fabsf(p[t + 256]) + fabsf(p[t + 512]) + fabsf(p[t + 768]);
    __syncthreads();
    for (int o = 128; o > 0; o >>= 1) { if (t < o) sh[t] += sh[t + o]; __syncthreads(); }
    if (t == 0) g_partial[b] = sh[0];
}
__global__ void __launch_bounds__(256) reduce_absw_2() {
    __shared__ float sh[256];
    int t = threadIdx.x;
    float s = g_partial[t] + g_partial[t + 256];
    if (t < 64) s += g_partial[t + 512];
    sh[t] = s;
    __syncthreads();
    for (int o = 128; o > 0; o >>= 1) { if (t < o) sh[t] += sh[t + o]; __syncthreads(); }
    if (t == 0) g_E = sh[0] / (float)NW_ELEM;
}

// ---------------- 2. quantize acts -> padded s8 packs ------------------------
__global__ void __launch_bounds__(256) quantize_x(const float* __restrict__ x) {
    int idx = blockIdx.x * 256 + threadIdx.x;
    if (idx >= NB * HP * WP * 64) return;
    int c4 = idx & 63;
    int t  = idx >> 6;
    int wp = t % WP; t /= WP;
    int hp = t % HP;
    int n  = t / HP;
    int pack = 0;
    if (hp >= 1 && hp <= HH && wp >= 1 && wp <= WW) {
        const float4 v = *reinterpret_cast<const float4*>(
            x + (((size_t)(n * HH + (hp - 1)) * WW + (wp - 1)) * CI + c4 * 4));
        int a0 = __float2int_rn(fminf(1.0f, fabsf(v.x)) * 7.0f);
        int a1 = __float2int_rn(fminf(1.0f, fabsf(v.y)) * 7.0f);
        int a2 = __float2int_rn(fminf(1.0f, fabsf(v.z)) * 7.0f);
        int a3 = __float2int_rn(fminf(1.0f, fabsf(v.w)) * 7.0f);
        pack = (a0 & 0xff) | ((a1 & 0xff) << 8) | ((a2 & 0xff) << 16) | ((a3 & 0xff) << 24);
    }
    g_act[idx] = pack;
}

// ---------------- 3. weight transform: U2 = (2G) w (2G)^T -> bf16 ------------
__global__ void __launch_bounds__(256) wg_transform(const float* __restrict__ W) {
    int idx = blockIdx.x * 256 + threadIdx.x;
    if (idx >= CO * CI) return;
    int ci = idx & 255;
    int co = idx >> 8;
    int w[3][3];
#pragma unroll
    for (int kh = 0; kh < 3; kh++)
#pragma unroll
        for (int kw = 0; kw < 3; kw++) {
            float f = W[((size_t)((kh * 3 + kw) * CI + ci)) * CO + co];
            w[kh][kw] = (f > 0.0f) - (f < 0.0f);
        }
    int t[4][3];
#pragma unroll
    for (int c = 0; c < 3; c++) {
        t[0][c] = 2 * w[0][c];
        t[1][c] = w[0][c] + w[1][c] + w[2][c];
        t[2][c] = w[0][c] - w[1][c] + w[2][c];
        t[3][c] = 2 * w[2][c];
    }
#pragma unroll
    for (int i = 0; i < 4; i++) {
        int u[4];
        u[0] = 2 * t[i][0];
        u[1] = t[i][0] + t[i][1] + t[i][2];
        u[2] = t[i][0] - t[i][1] + t[i][2];
        u[3] = 2 * t[i][2];
#pragma unroll
        for (int j = 0; j < 4; j++)
            g_U[(((i * 4 + j) * CO + co) << 8) + ci] = __float2bfloat16((float)u[j]);
    }
}

// ---------------- 4. input transform: V = B^T d B -> bf16 --------------------
__global__ void __launch_bounds__(256) in_transform() {
    int idx = blockIdx.x * 256 + threadIdx.x;
    if (idx >= NT * 64) return;
    int cw = idx & 63;
    int T  = idx >> 6;
    int n  = T / NTPI;
    int rem = T - n * NTPI;
    int ti = rem / 28;
    int tj = rem - ti * 28;

    unsigned d[16];
#pragma unroll
    for (int r = 0; r < 4; r++)
#pragma unroll
        for (int c = 0; c < 4; c++)
            d[r * 4 + c] = (unsigned)g_act[((n * HP + 2 * ti + r) * WP + (2 * tj + c)) * 64 + cw];

    unsigned t0[4], t1[4], t2[4], t3[4];
#pragma unroll
    for (int c = 0; c < 4; c++) {
        t0[c] = __vsub4(d[0 * 4 + c], d[2 * 4 + c]);
        t1[c] = __vadd4(d[1 * 4 + c], d[2 * 4 + c]);
        t2[c] = __vsub4(d[2 * 4 + c], d[1 * 4 + c]);
        t3[c] = __vsub4(d[1 * 4 + c], d[3 * 4 + c]);
    }
    unsigned V[16];
#pragma unroll
    for (int i = 0; i < 4; i++) {
        const unsigned* t = (i == 0) ? t0 : (i == 1) ? t1 : (i == 2) ? t2 : t3;
        V[i * 4 + 0] = __vsub4(t[0], t[2]);
        V[i * 4 + 1] = __vadd4(t[1], t[2]);
        V[i * 4 + 2] = __vsub4(t[2], t[1]);
        V[i * 4 + 3] = __vsub4(t[1], t[3]);
    }
#pragma unroll
    for (int p = 0; p < 16; p++) {
        const unsigned v = V[p];
        union { __nv_bfloat16 h[4]; uint2 u; } o;
        o.h[0] = __float2bfloat16((float)(((int)(v << 24)) >> 24));
        o.h[1] = __float2bfloat16((float)(((int)(v << 16)) >> 24));
        o.h[2] = __float2bfloat16((float)(((int)(v <<  8)) >> 24));
        o.h[3] = __float2bfloat16((float)(((int)v) >> 24));
        *reinterpret_cast<uint2*>(&g_V[((size_t)p * NT + T) * CI + cw * 4]) = o.u;
    }
}

// ---------------- 5. B-stationary bf16 HMMA GEMM -----------------------------
// grid (392, 16=pos); block 256 = 8 warps; CTA tile 64 tiles x 256 co.
// warp w: cols [w*32, w*32+32), warp tile 64x32 (ma=4, na=4) = 16 HMMA/k-step.
__global__ void __launch_bounds__(256, 2) wino_gemm() {
    __shared__ char sbuf[NSTG * STAGE_B];        // 46080 B

    const int tid = threadIdx.x;
    const int lane = tid & 31, wid = tid >> 5;
    const int pbase = blockIdx.x * 64;
    const int pos = blockIdx.y;
    const uint32_t sb = smem_u32(sbuf);

    // producer: threads 0-127 fill A (row tid>>1, half tid&1);
    //           all 256 threads fill B (row tid, both halves)
    const bool doA = tid < 128;
    const int arow = tid >> 1, ahalf = tid & 1;
    const char* aSrc = (const char*)g_V + ((size_t)pos * NT + pbase + arow) * 512 + ahalf * 16;
    const uint32_t aDst = (uint32_t)(arow * ROWPAD + ahalf * 16);
    const char* bSrc = (const char*)g_U + ((size_t)pos * CO + tid) * 512;
    const uint32_t bDst = (uint32_t)(A_SZ + tid * ROWPAD);

    // consumer: all warps share A rows 0-63; warp covers co block wid*32
    const uint32_t aoff = (uint32_t)((lane >> 2) * ROWPAD + (lane & 3) * 4);
    const uint32_t boff = (uint32_t)(A_SZ + (wid * 32 + (lane >> 2)) * ROWPAD + (lane & 3) * 4);

    // acc[ma(4)][na(4)][4]
    float acc[64];
#pragma unroll
    for (int e = 0; e < 64; e++) acc[e] = 0.0f;

#pragma unroll
    for (int s = 0; s < NSTG - 1; s++) {
        const uint32_t slot = sb + s * STAGE_B;
        if (doA) CP_ASYNC16(slot + aDst, aSrc + s * 32);
        CP_ASYNC16(slot + bDst, bSrc + s * 32);
        CP_ASYNC16(slot + bDst + 16, bSrc + s * 32 + 16);
        CP_COMMIT();
    }

    int slot = 0, loadSlot = NSTG - 1;
    for (int ks = 0; ks < NKS; ks++) {
        CP_WAIT(NSTG - 2);
        __syncthreads();

        {
            const int kn = ks + NSTG - 1;
            if (kn < NKS) {
                const uint32_t sl = sb + loadSlot * STAGE_B;
                if (doA) CP_ASYNC16(sl + aDst, aSrc + kn * 32);
                CP_ASYNC16(sl + bDst, bSrc + kn * 32);
                CP_ASYNC16(sl + bDst + 16, bSrc + kn * 32 + 16);
            }
            CP_COMMIT();
        }

        const char* s = sbuf + slot * STAGE_B;
        uint32_t af[4][4];
#pragma unroll
        for (int ma = 0; ma < 4; ma++) {
            const char* ab = s + aoff + ma * (16 * ROWPAD);
            af[ma][0] = *(const uint32_t*)(ab);
            af[ma][1] = *(const uint32_t*)(ab + 8 * ROWPAD);
            af[ma][2] = *(const uint32_t*)(ab + 16);
            af[ma][3] = *(const uint32_t*)(ab + 8 * ROWPAD + 16);
        }
#pragma unroll
        for (int na = 0; na < 4; na++) {
            const char* bb = s + boff + na * (8 * ROWPAD);
            const uint32_t bf0 = *(const uint32_t*)(bb);
            const uint32_t bf1 = *(const uint32_t*)(bb + 16);
#pragma unroll
            for (int ma = 0; ma < 4; ma++)
                hmma16816(&acc[(ma * 4 + na) * 4], af[ma][0], af[ma][1],
                          af[ma][2], af[ma][3], bf0, bf1);
        }

        slot++;     if (slot == NSTG) slot = 0;
        loadSlot++; if (loadSlot == NSTG) loadSlot = 0;
    }

    // store fp32 C
    float* Cb = g_C + (size_t)pos * NT * CO;
    const int row0 = pbase + (lane >> 2);
    const int col0 = wid * 32 + (lane & 3) * 2;
#pragma unroll
    for (int ma = 0; ma < 4; ma++) {
#pragma unroll
        for (int na = 0; na < 4; na++) {
            const float* a4 = &acc[(ma * 4 + na) * 4];
            const int row = row0 + ma * 16;
            const int col = col0 + na * 8;
            *reinterpret_cast<float2*>(Cb + (size_t)row * CO + col) =
                make_float2(a4[0], a4[1]);
            *reinterpret_cast<float2*>(Cb + (size_t)(row + 8) * CO + col) =
                make_float2(a4[2], a4[3]);
        }
    }
}

// ---------------- 6. output transform: Y = A^T M A, scale, bias --------------
__global__ void __launch_bounds__(256) out_transform(const float* __restrict__ bias,
                                                     float* __restrict__ out) {
    const int lane = threadIdx.x & 31, wid = threadIdx.x >> 5;
    const int T = blockIdx.x * 8 + wid;
    const int n  = T / NTPI;
    const int rem = T - n * NTPI;
    const int ti = rem / 28;
    const int tj = rem - ti * 28;
    const float scale = g_E * (1.0f / 28.0f);

#pragma unroll 1
    for (int cb = 0; cb < 8; cb++) {
        const int co = cb * 32 + lane;
        float m[16];
#pragma unroll
        for (int p = 0; p < 16; p++)
            m[p] = g_C[((size_t)p * NT + T) * CO + co];

        float P0[4], P1[4];
#pragma unroll
        for (int c = 0; c < 4; c++) {
            P0[c] = m[0 * 4 + c] + m[1 * 4 + c] + m[2 * 4 + c];
            P1[c] = m[1 * 4 + c] - m[2 * 4 + c] - m[3 * 4 + c];
        }
        const float y00 = P0[0] + P0[1] + P0[2];
        const float y01 = P0[1] - P0[2] - P0[3];
        const float y10 = P1[0] + P1[1] + P1[2];
        const float y11 = P1[1] - P1[2] - P1[3];

        const float bv = bias[co];
        float* o00 = out + (((size_t)(n * HH + 2 * ti) * WW + 2 * tj) * CO + co);
        o00[0]                  = y00 * scale + bv;
        o00[CO]                 = y01 * scale + bv;
        o00[(size_t)WW*CO]      = y10 * scale + bv;
        o00[(size_t)WW*CO + CO] = y11 * scale + bv;
    }
}

// ---------------- launch -----------------------------------------------------
extern "C" void kernel_launch(void* const* d_in, const int* in_sizes, int n_in,
                              void* d_out, int out_size) {
    const float* x = (const float*)d_in[0];
    const float* W = (const float*)d_in[1];
    const float* b = (const float*)d_in[2];
    float* out = (float*)d_out;

    int qtot = NB * HP * WP * 64;
    quantize_x<<<(qtot + 255) / 256, 256>>>(x);
    reduce_absw_1<<<576, 256>>>(W);
    reduce_absw_2<<<1, 256>>>();
    wg_transform<<<CO * CI / 256, 256>>>(W);
    in_transform<<<(NT * 64 + 255) / 256, 256>>>();
    wino_gemm<<<dim3(392, 16), 256>>>();
    out_transform<<<NT / 8, 256>>>(b, out);
}

// round 17
// speedup vs baseline: 1.2741x; 1.2741x over previous
#include <cuda_runtime.h>
#include <cuda_bf16.h>
#include <stdint.h>

// ---------------- problem constants ----------------------------------------
#define NB   32
#define HH   56
#define WW   56
#define CI   256
#define CO   256
#define HP   58
#define WP   58
#define NW_ELEM (9*CI*CO)        // 589824
#define NTPI 784                 // 28x28 tiles per image
#define NT   (NB*NTPI)           // 25088 Winograd tiles
#define MT   196                 // 25088/128 M-tiles
#define NKS  16                  // K = 256 in 16-element bf16 steps (32 B)

#define STAGES      3
#define ROWPAD      48
#define A_BYTES_I   (128*ROWPAD)             // 6144
#define STAGE_BYTES (2*128*ROWPAD)           // 12288

// ---------------- device scratch --------------------------------------------
__device__ int            g_act[NB * HP * WP * 64];        // padded s8 acts, 27.5 MB
__device__ __nv_bfloat16  g_V[(size_t)16 * NT * CI];       // transformed acts, 205 MB
__device__ __nv_bfloat16  g_U[16 * CO * CI];               // transformed weights, 2 MB
__device__ float          g_C[(size_t)16 * NT * CO];       // GEMM out fp32, 411 MB
__device__ float g_partial[576];
__device__ float g_E;

// ---------------- PTX helpers ------------------------------------------------
__device__ __forceinline__ uint32_t smem_u32(const void* p) {
    uint32_t a;
    asm("{ .reg .u64 t; cvta.to.shared.u64 t, %1; cvt.u32.u64 %0, t; }" : "=r"(a) : "l"(p));
    return a;
}
#define CP_ASYNC16(dst, src) \
    asm volatile("cp.async.cg.shared.global [%0], [%1], 16;" \
        :: "r"(dst), "l"(__cvta_generic_to_global(src)))
#define CP_COMMIT() asm volatile("cp.async.commit_group;" ::: "memory")
#define CP_WAIT(n)  asm volatile("cp.async.wait_group %0;" :: "n"(n) : "memory")

__device__ __forceinline__ void hmma16816(float* d, uint32_t a0, uint32_t a1,
                                          uint32_t a2, uint32_t a3,
                                          uint32_t b0, uint32_t b1) {
    asm volatile(
        "mma.sync.aligned.m16n8k16.row.col.f32.bf16.bf16.f32 "
        "{%0,%1,%2,%3}, {%4,%5,%6,%7}, {%8,%9}, {%0,%1,%2,%3};"
        : "+f"(d[0]), "+f"(d[1]), "+f"(d[2]), "+f"(d[3])
        : "r"(a0), "r"(a1), "r"(a2), "r"(a3), "r"(b0), "r"(b1));
}

// ---------------- 1a/1b. E = mean|W| -----------------------------------------
__global__ void __launch_bounds__(256) reduce_absw_1(const float* __restrict__ W) {
    __shared__ float sh[256];
    int b = blockIdx.x, t = threadIdx.x;
    const float* p = W + b * 1024;
    sh[t] = fabsf(p[t]) + fabsf(p[t + 256]) + fabsf(p[t + 512]) + fabsf(p[t + 768]);
    __syncthreads();
    for (int o = 128; o > 0; o >>= 1) { if (t < o) sh[t] += sh[t + o]; __syncthreads(); }
    if (t == 0) g_partial[b] = sh[0];
}
__global__ void __launch_bounds__(256) reduce_absw_2() {
    __shared__ float sh[256];
    int t = threadIdx.x;
    float s = g_partial[t] + g_partial[t + 256];
    if (t < 64) s += g_partial[t + 512];
    sh[t] = s;
    __syncthreads();
    for (int o = 128; o > 0; o >>= 1) { if (t < o) sh[t] += sh[t + o]; __syncthreads(); }
    if (t == 0) g_E = sh[0] / (float)NW_ELEM;
}

// ---------------- 2. quantize acts -> padded s8 packs ------------------------
__global__ void __launch_bounds__(256) quantize_x(const float* __restrict__ x) {
    int idx = blockIdx.x * 256 + threadIdx.x;
    if (idx >= NB * HP * WP * 64) return;
    int c4 = idx & 63;
    int t  = idx >> 6;
    int wp = t % WP; t /= WP;
    int hp = t % HP;
    int n  = t / HP;
    int pack = 0;
    if (hp >= 1 && hp <= HH && wp >= 1 && wp <= WW) {
        const float4 v = *reinterpret_cast<const float4*>(
            x + (((size_t)(n * HH + (hp - 1)) * WW + (wp - 1)) * CI + c4 * 4));
        int a0 = __float2int_rn(fminf(1.0f, fabsf(v.x)) * 7.0f);
        int a1 = __float2int_rn(fminf(1.0f, fabsf(v.y)) * 7.0f);
        int a2 = __float2int_rn(fminf(1.0f, fabsf(v.z)) * 7.0f);
        int a3 = __float2int_rn(fminf(1.0f, fabsf(v.w)) * 7.0f);
        pack = (a0 & 0xff) | ((a1 & 0xff) << 8) | ((a2 & 0xff) << 16) | ((a3 & 0xff) << 24);
    }
    g_act[idx] = pack;
}

// ---------------- 3. weight transform: U2 = (2G) w (2G)^T -> bf16 ------------
__global__ void __launch_bounds__(256) wg_transform(const float* __restrict__ W) {
    int idx = blockIdx.x * 256 + threadIdx.x;
    if (idx >= CO * CI) return;
    int ci = idx & 255;
    int co = idx >> 8;
    int w[3][3];
#pragma unroll
    for (int kh = 0; kh < 3; kh++)
#pragma unroll
        for (int kw = 0; kw < 3; kw++) {
            float f = W[((size_t)((kh * 3 + kw) * CI + ci)) * CO + co];
            w[kh][kw] = (f > 0.0f) - (f < 0.0f);
        }
    int t[4][3];
#pragma unroll
    for (int c = 0; c < 3; c++) {
        t[0][c] = 2 * w[0][c];
        t[1][c] = w[0][c] + w[1][c] + w[2][c];
        t[2][c] = w[0][c] - w[1][c] + w[2][c];
        t[3][c] = 2 * w[2][c];
    }
#pragma unroll
    for (int i = 0; i < 4; i++) {
        int u[4];
        u[0] = 2 * t[i][0];
        u[1] = t[i][0] + t[i][1] + t[i][2];
        u[2] = t[i][0] - t[i][1] + t[i][2];
        u[3] = 2 * t[i][2];
#pragma unroll
        for (int j = 0; j < 4; j++)
            g_U[(((i * 4 + j) * CO + co) << 8) + ci] = __float2bfloat16((float)u[j]);
    }
}

// ---------------- 4. input transform: V = B^T d B -> bf16 --------------------
__global__ void __launch_bounds__(256) in_transform() {
    int idx = blockIdx.x * 256 + threadIdx.x;
    if (idx >= NT * 64) return;
    int cw = idx & 63;
    int T  = idx >> 6;
    int n  = T / NTPI;
    int rem = T - n * NTPI;
    int ti = rem / 28;
    int tj = rem - ti * 28;

    unsigned d[16];
#pragma unroll
    for (int r = 0; r < 4; r++)
#pragma unroll
        for (int c = 0; c < 4; c++)
            d[r * 4 + c] = (unsigned)g_act[((n * HP + 2 * ti + r) * WP + (2 * tj + c)) * 64 + cw];

    unsigned t0[4], t1[4], t2[4], t3[4];
#pragma unroll
    for (int c = 0; c < 4; c++) {
        t0[c] = __vsub4(d[0 * 4 + c], d[2 * 4 + c]);
        t1[c] = __vadd4(d[1 * 4 + c], d[2 * 4 + c]);
        t2[c] = __vsub4(d[2 * 4 + c], d[1 * 4 + c]);
        t3[c] = __vsub4(d[1 * 4 + c], d[3 * 4 + c]);
    }
    unsigned V[16];
#pragma unroll
    for (int i = 0; i < 4; i++) {
        const unsigned* t = (i == 0) ? t0 : (i == 1) ? t1 : (i == 2) ? t2 : t3;
        V[i * 4 + 0] = __vsub4(t[0], t[2]);
        V[i * 4 + 1] = __vadd4(t[1], t[2]);
        V[i * 4 + 2] = __vsub4(t[2], t[1]);
        V[i * 4 + 3] = __vsub4(t[1], t[3]);
    }
#pragma unroll
    for (int p = 0; p < 16; p++) {
        const unsigned v = V[p];
        union { __nv_bfloat16 h[4]; uint2 u; } o;
        o.h[0] = __float2bfloat16((float)(((int)(v << 24)) >> 24));
        o.h[1] = __float2bfloat16((float)(((int)(v << 16)) >> 24));
        o.h[2] = __float2bfloat16((float)(((int)(v <<  8)) >> 24));
        o.h[3] = __float2bfloat16((float)(((int)v) >> 24));
        *reinterpret_cast<uint2*>(&g_V[((size_t)p * NT + T) * CI + cw * 4]) = o.u;
    }
}

// ---------------- 5. 16 batched bf16 HMMA GEMMs ------------------------------
// grid (2=nbase, 196=M-tile, 16=pos) — paired nbase CTAs adjacent in bid so
// the shared V slice is an L2 hit for the second. Body identical to R12.
__global__ void __launch_bounds__(256, 2) wino_gemm() {
    __shared__ char sbuf[STAGES * STAGE_BYTES];        // 36864 B

    const int tid = threadIdx.x;
    const int pbase = blockIdx.y * 128;
    const int nbase = blockIdx.x * 128;
    const int pos = blockIdx.z;

    const int pr = tid >> 1, half = tid & 1;
    const char* aBase = (const char*)g_V + ((size_t)pos * NT + pbase + pr) * 512 + half * 16;
    const char* bBase = (const char*)g_U + ((size_t)pos * CO + nbase + pr) * 512 + half * 16;
    const uint32_t dstOff = pr * ROWPAD + half * 16;
    const uint32_t sb = smem_u32(sbuf);

    const int lane = tid & 31, wid = tid >> 5;
    const int mgrp = wid & 3;
    const int ngrp = wid >> 2;
    const uint32_t aoff = (uint32_t)((mgrp * 32 + (lane >> 2)) * ROWPAD + (lane & 3) * 4);
    const uint32_t boff = (uint32_t)((ngrp * 64 + (lane >> 2)) * ROWPAD + (lane & 3) * 4) + A_BYTES_I;

    float acc[2][8][4];
#pragma unroll
    for (int ma = 0; ma < 2; ma++)
#pragma unroll
        for (int na = 0; na < 8; na++)
#pragma unroll
            for (int j = 0; j < 4; j++) acc[ma][na][j] = 0.0f;

#pragma unroll
    for (int ks = 0; ks < STAGES - 1; ks++) {
        const uint32_t slot = sb + ks * STAGE_BYTES;
        CP_ASYNC16(slot + dstOff, aBase + ks * 32);
        CP_ASYNC16(slot + A_BYTES_I + dstOff, bBase + ks * 32);
        CP_COMMIT();
    }

    int slotIdx = 0;
    int loadSlot = STAGES - 1;
    for (int ks = 0; ks < NKS; ks++) {
        CP_WAIT(STAGES - 2);
        __syncthreads();

        {
            const int kn = ks + STAGES - 1;
            if (kn < NKS) {
                const uint32_t slot = sb + loadSlot * STAGE_BYTES;
                CP_ASYNC16(slot + dstOff, aBase + kn * 32);
                CP_ASYNC16(slot + A_BYTES_I + dstOff, bBase + kn * 32);
            }
            CP_COMMIT();
        }

        const char* s = sbuf + slotIdx * STAGE_BYTES;
        uint32_t af[2][4];
#pragma unroll
        for (int ma = 0; ma < 2; ma++) {
            const char* ab = s + aoff + ma * (16 * ROWPAD);
            af[ma][0] = *(const uint32_t*)(ab);
            af[ma][1] = *(const uint32_t*)(ab + 8 * ROWPAD);
            af[ma][2] = *(const uint32_t*)(ab + 16);
            af[ma][3] = *(const uint32_t*)(ab + 8 * ROWPAD + 16);
        }
        uint32_t bf[8][2];
#pragma unroll
        for (int na = 0; na < 8; na++) {
            const char* bb = s + boff + na * (8 * ROWPAD);
            bf[na][0] = *(const uint32_t*)(bb);
            bf[na][1] = *(const uint32_t*)(bb + 16);
        }
#pragma unroll
        for (int na = 0; na < 8; na++)
#pragma unroll
            for (int ma = 0; ma < 2; ma++)
                hmma16816(acc[ma][na], af[ma][0], af[ma][1], af[ma][2], af[ma][3],
                          bf[na][0], bf[na][1]);

        slotIdx++;  if (slotIdx == STAGES) slotIdx = 0;
        loadSlot++; if (loadSlot == STAGES) loadSlot = 0;
    }

    // store fp32 C (exact integers)
    const int row0 = pbase + mgrp * 32 + (lane >> 2);
    const int col0 = nbase + ngrp * 64 + (lane & 3) * 2;
    float* Cb = g_C + (size_t)pos * NT * CO;
#pragma unroll
    for (int ma = 0; ma < 2; ma++) {
#pragma unroll
        for (int na = 0; na < 8; na++) {
            const int row = row0 + ma * 16;
            const int col = col0 + na * 8;
            *reinterpret_cast<float2*>(Cb + (size_t)row * CO + col) =
                make_float2(acc[ma][na][0], acc[ma][na][1]);
            *reinterpret_cast<float2*>(Cb + (size_t)(row + 8) * CO + col) =
                make_float2(acc[ma][na][2], acc[ma][na][3]);
        }
    }
}

// ---------------- 6. output transform: Y = A^T M A, scale, bias --------------
__global__ void __launch_bounds__(256) out_transform(const float* __restrict__ bias,
                                                     float* __restrict__ out) {
    const int lane = threadIdx.x & 31, wid = threadIdx.x >> 5;
    const int T = blockIdx.x * 8 + wid;
    const int n  = T / NTPI;
    const int rem = T - n * NTPI;
    const int ti = rem / 28;
    const int tj = rem - ti * 28;
    const float scale = g_E * (1.0f / 28.0f);

#pragma unroll 1
    for (int cb = 0; cb < 8; cb++) {
        const int co = cb * 32 + lane;
        float m[16];
#pragma unroll
        for (int p = 0; p < 16; p++)
            m[p] = g_C[((size_t)p * NT + T) * CO + co];

        float P0[4], P1[4];
#pragma unroll
        for (int c = 0; c < 4; c++) {
            P0[c] = m[0 * 4 + c] + m[1 * 4 + c] + m[2 * 4 + c];
            P1[c] = m[1 * 4 + c] - m[2 * 4 + c] - m[3 * 4 + c];
        }
        const float y00 = P0[0] + P0[1] + P0[2];
        const float y01 = P0[1] - P0[2] - P0[3];
        const float y10 = P1[0] + P1[1] + P1[2];
        const float y11 = P1[1] - P1[2] - P1[3];

        const float bv = bias[co];
        float* o00 = out + (((size_t)(n * HH + 2 * ti) * WW + 2 * tj) * CO + co);
        o00[0]                  = y00 * scale + bv;
        o00[CO]                 = y01 * scale + bv;
        o00[(size_t)WW*CO]      = y10 * scale + bv;
        o00[(size_t)WW*CO + CO] = y11 * scale + bv;
    }
}

// ---------------- launch -----------------------------------------------------
extern "C" void kernel_launch(void* const* d_in, const int* in_sizes, int n_in,
                              void* d_out, int out_size) {
    const float* x = (const float*)d_in[0];
    const float* W = (const float*)d_in[1];
    const float* b = (const float*)d_in[2];
    float* out = (float*)d_out;

    int qtot = NB * HP * WP * 64;
    quantize_x<<<(qtot + 255) / 256, 256>>>(x);
    reduce_absw_1<<<576, 256>>>(W);
    reduce_absw_2<<<1, 256>>>();
    wg_transform<<<CO * CI / 256, 256>>>(W);
    in_transform<<<(NT * 64 + 255) / 256, 256>>>();
    wino_gemm<<<dim3(2, MT, 16), 256>>>();
    out_transform<<<NT / 8, 256>>>(b, out);
}